// round 3
// baseline (speedup 1.0000x reference)
#include <cuda_runtime.h>
#include <cuda_bf16.h>
#include <cstdint>

// ---------------------------------------------------------------------------
// Problem sizes (fixed by the dataset)
// ---------------------------------------------------------------------------
#define B_SZ 128
#define K_SZ 1024
#define T_SZ 256
#define U_SZ 1024
#define M_SZ (B_SZ * T_SZ)   // 32768

#define ALPHA_C 0.9f
#define BETA_C  0.85f

// ---------------------------------------------------------------------------
// Device scratch (static allocation — dynamic alloc is forbidden)
// ---------------------------------------------------------------------------
__device__ __nv_bfloat16 g_Ahi[(size_t)M_SZ * K_SZ];  // x^T hi [m,k] (64 MB)
__device__ __nv_bfloat16 g_Alo[(size_t)M_SZ * K_SZ];  // x^T lo [m,k] (64 MB)
__device__ __nv_bfloat16 g_Whi[(size_t)U_SZ * K_SZ];  // W^T hi [u,k] (2 MB)
__device__ __nv_bfloat16 g_Wlo[(size_t)U_SZ * K_SZ];  // W^T lo [u,k] (2 MB)
__device__ float         g_H[(size_t)M_SZ * U_SZ];    // h[b,t,u] (134 MB)

// ---------------------------------------------------------------------------
// PTX helpers (sm_80-era instructions only — compute_100 base target!)
// ---------------------------------------------------------------------------
__device__ __forceinline__ uint32_t smem_u32(const void* p) {
    uint32_t a;
    asm("{ .reg .u64 t; cvta.to.shared.u64 t, %1; cvt.u32.u64 %0, t; }"
        : "=r"(a) : "l"(p));
    return a;
}

#define CP_ASYNC16(dst, src) \
    asm volatile("cp.async.cg.shared.global [%0], [%1], 16;" :: "r"(dst), "l"(src))
#define CP_COMMIT() asm volatile("cp.async.commit_group;")
#define CP_WAIT(n)  asm volatile("cp.async.wait_group %0;" :: "n"(n))

__device__ __forceinline__ void ldsm4(uint32_t* r, uint32_t addr) {
    asm volatile("ldmatrix.sync.aligned.m8n8.x4.shared.b16 {%0,%1,%2,%3}, [%4];"
                 : "=r"(r[0]), "=r"(r[1]), "=r"(r[2]), "=r"(r[3]) : "r"(addr));
}

__device__ __forceinline__ void mma16816(float* c, const uint32_t* a, const uint32_t* b) {
    asm volatile(
        "mma.sync.aligned.m16n8k16.row.col.f32.bf16.bf16.f32 "
        "{%0,%1,%2,%3}, {%4,%5,%6,%7}, {%8,%9}, {%0,%1,%2,%3};"
        : "+f"(c[0]), "+f"(c[1]), "+f"(c[2]), "+f"(c[3])
        : "r"(a[0]), "r"(a[1]), "r"(a[2]), "r"(a[3]), "r"(b[0]), "r"(b[1]));
}

// ---------------------------------------------------------------------------
// hi/lo bf16 split: x == hi + lo + O(2^-17 * x)
// ---------------------------------------------------------------------------
__device__ __forceinline__ void split_bf16(float f, __nv_bfloat16& hi, __nv_bfloat16& lo) {
    hi = __float2bfloat16_rn(f);
    lo = __float2bfloat16_rn(f - __bfloat162float(hi));
}

// ---------------------------------------------------------------------------
// Kernel 1a: transpose+split x[b,k,t] -> A_hi/A_lo[(b*T+t), k]
// ---------------------------------------------------------------------------
__global__ void __launch_bounds__(256) transpose_x_kernel(const float* __restrict__ x) {
    __shared__ float s[32][33];
    const int b  = blockIdx.z;
    const int k0 = blockIdx.y * 32;
    const int t0 = blockIdx.x * 32;
    const int tx = threadIdx.x;
    const int ty = threadIdx.y;

    const float* xp = x + (size_t)b * K_SZ * T_SZ;
#pragma unroll
    for (int i = 0; i < 4; i++) {
        s[ty + i * 8][tx] = xp[(size_t)(k0 + ty + i * 8) * T_SZ + (t0 + tx)];
    }
    __syncthreads();
    const size_t rowbase = (size_t)b * T_SZ * K_SZ;
#pragma unroll
    for (int i = 0; i < 4; i++) {
        const int t = t0 + ty + i * 8;
        __nv_bfloat16 hi, lo;
        split_bf16(s[tx][ty + i * 8], hi, lo);
        const size_t idx = rowbase + (size_t)t * K_SZ + (k0 + tx);
        g_Ahi[idx] = hi;
        g_Alo[idx] = lo;
    }
}

// ---------------------------------------------------------------------------
// Kernel 1b: transpose+split W[k,u] -> W_hi/W_lo[u,k]
// ---------------------------------------------------------------------------
__global__ void __launch_bounds__(256) transpose_w_kernel(const float* __restrict__ W) {
    __shared__ float s[32][33];
    const int k0 = blockIdx.y * 32;
    const int u0 = blockIdx.x * 32;
    const int tx = threadIdx.x;
    const int ty = threadIdx.y;

#pragma unroll
    for (int i = 0; i < 4; i++) {
        s[ty + i * 8][tx] = W[(size_t)(k0 + ty + i * 8) * U_SZ + (u0 + tx)];
    }
    __syncthreads();
#pragma unroll
    for (int i = 0; i < 4; i++) {
        const int u = u0 + ty + i * 8;
        __nv_bfloat16 hi, lo;
        split_bf16(s[tx][ty + i * 8], hi, lo);
        const size_t idx = (size_t)u * K_SZ + (k0 + tx);
        g_Whi[idx] = hi;
        g_Wlo[idx] = lo;
    }
}

// ---------------------------------------------------------------------------
// Kernel 2: mma.sync bf16 GEMM with 3-way hi/lo split (virtual K' = 3072)
//   H[m,u] = A_hi·W_hi + A_hi·W_lo + A_lo·W_hi   (fp32 accum)
//   BM=128, BN=128, BK=64, 8 warps (warp tile 32x64), 3-stage cp.async.
// ---------------------------------------------------------------------------
#define BM 128
#define BN 128
#define BK 64
#define NKT 48                       // 3 passes x 16 k-tiles
#define STAGE_BYTES 32768            // A 16KB + B 16KB
#define NSTAGE 3
#define GEMM_SMEM (NSTAGE * STAGE_BYTES)   // 98304

__device__ __forceinline__ void gemm_tile_srcs(int kt, const __nv_bfloat16*& As,
                                               const __nv_bfloat16*& Ws, int& koff) {
    const int pass = kt >> 4;            // 0: hi*hi, 1: hi*lo, 2: lo*hi
    koff = (kt & 15) * BK;
    As = (pass == 2) ? g_Alo : g_Ahi;
    Ws = (pass == 1) ? g_Wlo : g_Whi;
}

__global__ void __launch_bounds__(256, 2) gemm_mma_kernel() {
    extern __shared__ char smem[];
    const uint32_t smem_b = smem_u32(smem);

    const int tid = threadIdx.x;
    const int wid = tid >> 5;
    const int lane = tid & 31;
    const int wm = wid & 3;              // 4 warps along M (4*32 = 128)
    const int wn = wid >> 2;             // 2 warps along N (2*64 = 128)
    const int m0 = blockIdx.y * BM;
    const int n0 = blockIdx.x * BN;

    float acc[2][8][4];
#pragma unroll
    for (int i = 0; i < 2; i++)
#pragma unroll
        for (int j = 0; j < 8; j++)
#pragma unroll
            for (int k = 0; k < 4; k++) acc[i][j][k] = 0.0f;

    // ---- cp.async tile loader: 4 chunks A + 4 chunks B per thread (16B each)
    auto load_tile = [&](int kt, int stage) {
        const __nv_bfloat16 *As, *Ws;
        int koff;
        gemm_tile_srcs(kt, As, Ws, koff);
        const uint32_t sA = smem_b + stage * STAGE_BYTES;
        const uint32_t sB = sA + 16384;
        const __nv_bfloat16* Ap = As + (size_t)m0 * K_SZ + koff;
        const __nv_bfloat16* Bp = Ws + (size_t)n0 * K_SZ + koff;
#pragma unroll
        for (int i = 0; i < 4; i++) {
            const int idx = tid + i * 256;       // 0..1023
            const int row = idx >> 3;            // 0..127
            const int c   = idx & 7;             // 16B chunk in 128B row
            const uint32_t soff = (uint32_t)(row * 128 + ((c ^ (row & 7)) << 4));
            CP_ASYNC16(sA + soff, (const char*)(Ap + (size_t)row * K_SZ) + c * 16);
            CP_ASYNC16(sB + soff, (const char*)(Bp + (size_t)row * K_SZ) + c * 16);
        }
    };

    // ---- prologue: prefetch 2 stages
    load_tile(0, 0); CP_COMMIT();
    load_tile(1, 1); CP_COMMIT();

    for (int kt = 0; kt < NKT; kt++) {
        if (kt + 2 < NKT) {
            load_tile(kt + 2, (kt + 2) % NSTAGE);
            CP_COMMIT();
            CP_WAIT(2);
        } else if (kt + 1 < NKT) {
            CP_WAIT(1);
        } else {
            CP_WAIT(0);
        }
        __syncthreads();

        const int stage = kt % NSTAGE;
        const uint32_t sA = smem_b + stage * STAGE_BYTES;
        const uint32_t sB = sA + 16384;

#pragma unroll
        for (int ks = 0; ks < 4; ks++) {
            // A fragments: 2x ldmatrix.x4 (m16 x k16 each)
            uint32_t a[2][4];
#pragma unroll
            for (int im = 0; im < 2; im++) {
                const int row = wm * 32 + im * 16 + (lane & 15);
                const int c = ks * 2 + (lane >> 4);
                ldsm4(a[im], sA + (uint32_t)(row * 128 + ((c ^ (row & 7)) << 4)));
            }
            // B fragments: 4x ldmatrix.x4 -> 8 n8-frags
            uint32_t b[16];
#pragma unroll
            for (int ib = 0; ib < 4; ib++) {
                const int nrow = wn * 64 + ib * 16 + (lane & 7) + ((lane >> 4) << 3);
                const int c = ks * 2 + ((lane >> 3) & 1);
                ldsm4(&b[ib * 4], sB + (uint32_t)(nrow * 128 + ((c ^ (nrow & 7)) << 4)));
            }
#pragma unroll
            for (int im = 0; im < 2; im++)
#pragma unroll
                for (int fn = 0; fn < 8; fn++)
                    mma16816(acc[im][fn], a[im], &b[fn * 2]);
        }
        __syncthreads();
    }

    // ---- epilogue: write H (fp32)
    const int gid = lane >> 2;           // group 0..7
    const int tig = lane & 3;            // thread-in-group
#pragma unroll
    for (int im = 0; im < 2; im++) {
        const int r0 = m0 + wm * 32 + im * 16 + gid;
        float* H0 = g_H + (size_t)r0 * U_SZ + n0 + wn * 64 + tig * 2;
        float* H1 = H0 + 8 * U_SZ;       // rows gid+8
#pragma unroll
        for (int fn = 0; fn < 8; fn++) {
            *(float2*)(H0 + fn * 8) = make_float2(acc[im][fn][0], acc[im][fn][1]);
            *(float2*)(H1 + fn * 8) = make_float2(acc[im][fn][2], acc[im][fn][3]);
        }
    }
}

// ---------------------------------------------------------------------------
// Kernel 3: leaky-integrate-and-fire scan over time
//   thread g = b*U + u; reads H[(b*T+t)*U + u] (coalesced), writes out[t,b,u]
// ---------------------------------------------------------------------------
__global__ void __launch_bounds__(256) scan_kernel(float* __restrict__ out) {
    const int g = blockIdx.x * 256 + threadIdx.x;   // 0 .. B*U-1
    const int b = g >> 10;                          // U = 1024
    const float* hp = g_H + (size_t)b * T_SZ * U_SZ + (g & 1023);
    float* op = out + g;

    float v = 0.0f, syn = 0.0f;
#pragma unroll 4
    for (int t = 0; t < T_SZ; t++) {
        const float h = hp[(size_t)t * U_SZ];
        const float s = 1.0f / (1.0f + __expf(1.0f - v));   // sigmoid(v - 1)
        const float syn_n = ALPHA_C * syn + h;
        v = (BETA_C * v + syn) * (1.0f - s);
        syn = syn_n;
        op[(size_t)t * (B_SZ * U_SZ)] = s;
    }
}

// ---------------------------------------------------------------------------
// Launch
// ---------------------------------------------------------------------------
extern "C" void kernel_launch(void* const* d_in, const int* in_sizes, int n_in,
                              void* d_out, int out_size) {
    (void)in_sizes; (void)n_in; (void)out_size;
    const float* x = (const float*)d_in[0];   // [128, 1024, 256] fp32
    const float* W = (const float*)d_in[1];   // [1024, 1024] fp32
    float* out = (float*)d_out;               // [256, 128, 1024] fp32

    cudaFuncSetAttribute((const void*)gemm_mma_kernel,
                         cudaFuncAttributeMaxDynamicSharedMemorySize, GEMM_SMEM);

    transpose_x_kernel<<<dim3(T_SZ / 32, K_SZ / 32, B_SZ), dim3(32, 8)>>>(x);
    transpose_w_kernel<<<dim3(U_SZ / 32, K_SZ / 32), dim3(32, 8)>>>(W);
    gemm_mma_kernel<<<dim3(U_SZ / BN, M_SZ / BM), 256, GEMM_SMEM>>>();
    scan_kernel<<<(B_SZ * U_SZ) / 256, 256>>>(out);
}

// round 5
// speedup vs baseline: 1.0426x; 1.0426x over previous
#include <cuda_runtime.h>
#include <cuda_bf16.h>
#include <cstdint>

// ---------------------------------------------------------------------------
// Problem sizes (fixed by the dataset)
// ---------------------------------------------------------------------------
#define B_SZ 128
#define K_SZ 1024
#define T_SZ 256
#define U_SZ 1024
#define M_SZ (B_SZ * T_SZ)   // 32768

#define ALPHA_C 0.9f
#define BETA_C  0.85f

// ---------------------------------------------------------------------------
// Device scratch (static allocation — dynamic alloc is forbidden)
// ---------------------------------------------------------------------------
__device__ __nv_bfloat16 g_Ahi[(size_t)M_SZ * K_SZ];  // x^T hi [m,k] (64 MB)
__device__ __nv_bfloat16 g_Alo[(size_t)M_SZ * K_SZ];  // x^T lo [m,k] (64 MB)
__device__ __nv_bfloat16 g_Whi[(size_t)U_SZ * K_SZ];  // W^T hi [u,k] (2 MB)
__device__ __nv_bfloat16 g_Wlo[(size_t)U_SZ * K_SZ];  // W^T lo [u,k] (2 MB)
__device__ float         g_H[(size_t)M_SZ * U_SZ];    // h[b,t,u] (134 MB)

// ---------------------------------------------------------------------------
// PTX helpers (sm_80-era instructions only — compute_100 base target!)
// ---------------------------------------------------------------------------
__device__ __forceinline__ uint32_t smem_u32(const void* p) {
    uint32_t a;
    asm("{ .reg .u64 t; cvta.to.shared.u64 t, %1; cvt.u32.u64 %0, t; }"
        : "=r"(a) : "l"(p));
    return a;
}

#define CP_ASYNC16(dst, src) \
    asm volatile("cp.async.cg.shared.global [%0], [%1], 16;" :: "r"(dst), "l"(src))
#define CP_COMMIT() asm volatile("cp.async.commit_group;")
#define CP_WAIT(n)  asm volatile("cp.async.wait_group %0;" :: "n"(n))

__device__ __forceinline__ void ldsm4(uint32_t* r, uint32_t addr) {
    asm volatile("ldmatrix.sync.aligned.m8n8.x4.shared.b16 {%0,%1,%2,%3}, [%4];"
                 : "=r"(r[0]), "=r"(r[1]), "=r"(r[2]), "=r"(r[3]) : "r"(addr));
}

__device__ __forceinline__ void mma16816(float* c, const uint32_t* a, const uint32_t* b) {
    asm volatile(
        "mma.sync.aligned.m16n8k16.row.col.f32.bf16.bf16.f32 "
        "{%0,%1,%2,%3}, {%4,%5,%6,%7}, {%8,%9}, {%0,%1,%2,%3};"
        : "+f"(c[0]), "+f"(c[1]), "+f"(c[2]), "+f"(c[3])
        : "r"(a[0]), "r"(a[1]), "r"(a[2]), "r"(a[3]), "r"(b[0]), "r"(b[1]));
}

__device__ __forceinline__ float ex2f(float x) {
    float r;
    asm("ex2.approx.f32 %0, %1;" : "=f"(r) : "f"(x));
    return r;
}

// ---------------------------------------------------------------------------
// hi/lo bf16 split: x == hi + lo + O(2^-17 * x)
// ---------------------------------------------------------------------------
__device__ __forceinline__ void split_bf16(float f, __nv_bfloat16& hi, __nv_bfloat16& lo) {
    hi = __float2bfloat16_rn(f);
    lo = __float2bfloat16_rn(f - __bfloat162float(hi));
}

// ---------------------------------------------------------------------------
// Kernel 1a: transpose+split x[b,k,t] -> A_hi/A_lo[(b*T+t), k]
// ---------------------------------------------------------------------------
__global__ void __launch_bounds__(256) transpose_x_kernel(const float* __restrict__ x) {
    __shared__ float s[32][33];
    const int b  = blockIdx.z;
    const int k0 = blockIdx.y * 32;
    const int t0 = blockIdx.x * 32;
    const int tx = threadIdx.x;
    const int ty = threadIdx.y;

    const float* xp = x + (size_t)b * K_SZ * T_SZ;
#pragma unroll
    for (int i = 0; i < 4; i++) {
        s[ty + i * 8][tx] = xp[(size_t)(k0 + ty + i * 8) * T_SZ + (t0 + tx)];
    }
    __syncthreads();
    const size_t rowbase = (size_t)b * T_SZ * K_SZ;
#pragma unroll
    for (int i = 0; i < 4; i++) {
        const int t = t0 + ty + i * 8;
        __nv_bfloat16 hi, lo;
        split_bf16(s[tx][ty + i * 8], hi, lo);
        const size_t idx = rowbase + (size_t)t * K_SZ + (k0 + tx);
        g_Ahi[idx] = hi;
        g_Alo[idx] = lo;
    }
}

// ---------------------------------------------------------------------------
// Kernel 1b: transpose+split W[k,u] -> W_hi/W_lo[u,k]
// ---------------------------------------------------------------------------
__global__ void __launch_bounds__(256) transpose_w_kernel(const float* __restrict__ W) {
    __shared__ float s[32][33];
    const int k0 = blockIdx.y * 32;
    const int u0 = blockIdx.x * 32;
    const int tx = threadIdx.x;
    const int ty = threadIdx.y;

#pragma unroll
    for (int i = 0; i < 4; i++) {
        s[ty + i * 8][tx] = W[(size_t)(k0 + ty + i * 8) * U_SZ + (u0 + tx)];
    }
    __syncthreads();
#pragma unroll
    for (int i = 0; i < 4; i++) {
        const int u = u0 + ty + i * 8;
        __nv_bfloat16 hi, lo;
        split_bf16(s[tx][ty + i * 8], hi, lo);
        const size_t idx = (size_t)u * K_SZ + (k0 + tx);
        g_Whi[idx] = hi;
        g_Wlo[idx] = lo;
    }
}

// ---------------------------------------------------------------------------
// Kernel 2: fused 3-product bf16 GEMM
//   H[m,u] = A_hi·W_hi + A_hi·W_lo + A_lo·W_hi   (fp32 accum)
//   All three products computed per k-tile from one operand load:
//   stage = {A_hi 16K, A_lo 16K, W_hi 16K, W_lo 16K} = 64 KB, 2 stages.
//   BM=128, BN=128, BK=64, 8 warps (warp tile 32x64).
// ---------------------------------------------------------------------------
#define BM 128
#define BN 128
#define BK 64
#define NKT 16                        // k-tiles (K=1024 / BK)
#define TILE_B 16384                  // one 128x128B operand tile
#define STAGE_BYTES (4 * TILE_B)      // 64 KB
#define GEMM_SMEM (2 * STAGE_BYTES)   // 128 KB

__global__ void __launch_bounds__(256) gemm_mma_kernel() {
    extern __shared__ char smem[];
    const uint32_t smem_b = smem_u32(smem);

    const int tid = threadIdx.x;
    const int wid = tid >> 5;
    const int lane = tid & 31;
    const int wm = wid & 3;              // 4 warps along M (4*32 = 128)
    const int wn = wid >> 2;             // 2 warps along N (2*64 = 128)
    const int m0 = blockIdx.y * BM;
    const int n0 = blockIdx.x * BN;

    float acc[2][8][4];
#pragma unroll
    for (int i = 0; i < 2; i++)
#pragma unroll
        for (int j = 0; j < 8; j++)
#pragma unroll
            for (int k = 0; k < 4; k++) acc[i][j][k] = 0.0f;

    // ---- loader: 4 operand tiles per k-tile, 16 cp.async (16B) per thread.
    // hi tiles (needed first by the compute loop) are issued before lo tiles.
    auto load_tile = [&](int kt, int stage) {
        const int koff = kt * BK;
        const uint32_t sbase = smem_b + stage * STAGE_BYTES;
        const __nv_bfloat16* srcs[4] = {
            g_Ahi + (size_t)m0 * K_SZ + koff,      // -> slot 0
            g_Whi + (size_t)n0 * K_SZ + koff,      // -> slot 2
            g_Alo + (size_t)m0 * K_SZ + koff,      // -> slot 1
            g_Wlo + (size_t)n0 * K_SZ + koff       // -> slot 3
        };
        const uint32_t slot[4] = {0, 2, 1, 3};
#pragma unroll
        for (int t = 0; t < 4; t++) {
            const uint32_t sdst = sbase + slot[t] * TILE_B;
            const __nv_bfloat16* src = srcs[t];
#pragma unroll
            for (int i = 0; i < 4; i++) {
                const int idx = tid + i * 256;       // 0..1023
                const int row = idx >> 3;            // 0..127
                const int c   = idx & 7;             // 16B chunk in 128B row
                const uint32_t soff = (uint32_t)(row * 128 + ((c ^ (row & 7)) << 4));
                CP_ASYNC16(sdst + soff, (const char*)(src + (size_t)row * K_SZ) + c * 16);
            }
        }
    };

    // ---- prologue
    load_tile(0, 0);
    CP_COMMIT();

    for (int kt = 0; kt < NKT; kt++) {
        if (kt + 1 < NKT) {
            load_tile(kt + 1, (kt + 1) & 1);
            CP_COMMIT();
            CP_WAIT(1);
        } else {
            CP_WAIT(0);
        }
        __syncthreads();

        const uint32_t st = smem_b + (kt & 1) * STAGE_BYTES;
        const uint32_t sAhi = st;
        const uint32_t sAlo = st + TILE_B;
        const uint32_t sBhi = st + 2 * TILE_B;
        const uint32_t sBlo = st + 3 * TILE_B;

#pragma unroll
        for (int ks = 0; ks < 4; ks++) {
            // A fragments (hi and lo), loaded once, reused for 2/1 products
            uint32_t ahi[2][4], alo[2][4];
#pragma unroll
            for (int im = 0; im < 2; im++) {
                const int row = wm * 32 + im * 16 + (lane & 15);
                const int c = ks * 2 + (lane >> 4);
                const uint32_t off = (uint32_t)(row * 128 + ((c ^ (row & 7)) << 4));
                ldsm4(ahi[im], sAhi + off);
                ldsm4(alo[im], sAlo + off);
            }
            // B fragments (hi and lo)
            uint32_t bhi[16], blo[16];
#pragma unroll
            for (int ib = 0; ib < 4; ib++) {
                const int nrow = wn * 64 + ib * 16 + (lane & 7) + ((lane >> 4) << 3);
                const int c = ks * 2 + ((lane >> 3) & 1);
                const uint32_t off = (uint32_t)(nrow * 128 + ((c ^ (nrow & 7)) << 4));
                ldsm4(&bhi[ib * 4], sBhi + off);
                ldsm4(&blo[ib * 4], sBlo + off);
            }
            // 3 products into one accumulator
#pragma unroll
            for (int im = 0; im < 2; im++)
#pragma unroll
                for (int fn = 0; fn < 8; fn++) {
                    mma16816(acc[im][fn], ahi[im], &bhi[fn * 2]);
                    mma16816(acc[im][fn], ahi[im], &blo[fn * 2]);
                    mma16816(acc[im][fn], alo[im], &bhi[fn * 2]);
                }
        }
        __syncthreads();
    }

    // ---- epilogue: write H (fp32)
    const int gid = lane >> 2;           // group 0..7
    const int tig = lane & 3;            // thread-in-group
#pragma unroll
    for (int im = 0; im < 2; im++) {
        const int r0 = m0 + wm * 32 + im * 16 + gid;
        float* H0 = g_H + (size_t)r0 * U_SZ + n0 + wn * 64 + tig * 2;
        float* H1 = H0 + 8 * U_SZ;       // rows gid+8
#pragma unroll
        for (int fn = 0; fn < 8; fn++) {
            *(float2*)(H0 + fn * 8) = make_float2(acc[im][fn][0], acc[im][fn][1]);
            *(float2*)(H1 + fn * 8) = make_float2(acc[im][fn][2], acc[im][fn][3]);
        }
    }
}

// ---------------------------------------------------------------------------
// Kernel 3: leaky-integrate-and-fire scan over time
//   MUFU diet: EX2 only; reciprocal via bit-hack + 3 Newton steps (FMA pipe).
// ---------------------------------------------------------------------------
__global__ void __launch_bounds__(256) scan_kernel(float* __restrict__ out) {
    const int g = blockIdx.x * 256 + threadIdx.x;   // 0 .. B*U-1
    const int b = g >> 10;                          // U = 1024
    const float* hp = g_H + (size_t)b * T_SZ * U_SZ + (g & 1023);
    float* op = out + g;

    float v = 0.0f, syn = 0.0f;
    float h = hp[0];
#pragma unroll 4
    for (int t = 0; t < T_SZ; t++) {
        // prefetch next h early (independent of the serial v-chain)
        const float h_next = (t + 1 < T_SZ) ? hp[(size_t)(t + 1) * U_SZ] : 0.0f;

        // s = sigmoid(v - 1) = 1 / (1 + exp(1 - v))
        const float e = ex2f((1.0f - v) * 1.44269504f);
        const float d = 1.0f + e;
        float r = __uint_as_float(0x7EF311C3u - __float_as_uint(d));
        r = r * (2.0f - d * r);
        r = r * (2.0f - d * r);
        r = r * (2.0f - d * r);
        const float s = r;

        const float syn_n = ALPHA_C * syn + h;
        v = (BETA_C * v + syn) * (1.0f - s);
        syn = syn_n;
        op[(size_t)t * (B_SZ * U_SZ)] = s;
        h = h_next;
    }
}

// ---------------------------------------------------------------------------
// Launch
// ---------------------------------------------------------------------------
extern "C" void kernel_launch(void* const* d_in, const int* in_sizes, int n_in,
                              void* d_out, int out_size) {
    (void)in_sizes; (void)n_in; (void)out_size;
    const float* x = (const float*)d_in[0];   // [128, 1024, 256] fp32
    const float* W = (const float*)d_in[1];   // [1024, 1024] fp32
    float* out = (float*)d_out;               // [256, 128, 1024] fp32

    cudaFuncSetAttribute((const void*)gemm_mma_kernel,
                         cudaFuncAttributeMaxDynamicSharedMemorySize, GEMM_SMEM);

    transpose_x_kernel<<<dim3(T_SZ / 32, K_SZ / 32, B_SZ), dim3(32, 8)>>>(x);
    transpose_w_kernel<<<dim3(U_SZ / 32, K_SZ / 32), dim3(32, 8)>>>(W);
    gemm_mma_kernel<<<dim3(U_SZ / BN, M_SZ / BM), 256, GEMM_SMEM>>>();
    scan_kernel<<<(B_SZ * U_SZ) / 256, 256>>>(out);
}